// round 8
// baseline (speedup 1.0000x reference)
#include <cuda_runtime.h>
#include <cuda_fp16.h>
#include <math.h>
#include <string.h>

#define NN 100000
#define NE 3200000
#define FIN 128
#define RS 16          // fp32 row stride (64 B)
#define RH 8           // half2 per fp16 row (32 B)
#define NB 1000
#define NBLK 98        // ceil(NN / 1024)
#define ADJ_CAP (NE + 3 * NN + 64)
#define SCAT_BLOCKS ((NE / 2 + 255) / 256)
#define GEMM_BLOCKS ((NN + 255) / 256)

// Scratch (allocation-free: __device__ globals; zero-initialized at load)
static __device__ float   g_xa[NN * RS];          // x @ W1[:128] (self, fp32)
static __device__ __half2 g_xbh[(NN + 1) * RH];   // x @ W1[128:] (fp16; row NN = 0)
static __device__ float   g_h1a[NN * RS];         // h1 @ W2[:10] (fp32)
static __device__ __half2 g_h1bh[(NN + 1) * RH];  // h1 @ W2[10:] (fp16; row NN = 0)
static __device__ float   g_h2[NN * RS];          // layer-2 output
static __device__ float   g_pool[NB * RS];        // batch pool sums ([10] = count)
static __device__ int     g_deg[NN];              // real in-degree
static __device__ int     g_start[NN];            // CSR starts (padded prefix)
static __device__ int     g_cursor[NN];
static __device__ int     g_adj[ADJ_CAP];         // padded CSR adjacency
static __device__ int     g_bsum[NBLK];

__device__ __forceinline__ unsigned h2u(__half2 h) {
    unsigned u; memcpy(&u, &h, 4); return u;
}
__device__ __forceinline__ unsigned long long pk2(float lo, float hi) {
    unsigned long long r;
    asm("mov.b64 %0, {%1, %2};" : "=l"(r) : "f"(lo), "f"(hi));
    return r;
}
__device__ __forceinline__ void fma2(unsigned long long& d, unsigned long long a,
                                     unsigned long long b) {
    asm("fma.rn.f32x2 %0, %1, %2, %0;" : "+l"(d) : "l"(a), "l"(b));
}
__device__ __forceinline__ float2 upk2(unsigned long long v) {
    float2 f;
    asm("mov.b64 {%0, %1}, %2;" : "=f"(f.x), "=f"(f.y) : "l"(v));
    return f;
}

// ---------------------------------------------------------------------------
__global__ void k_zero() {
    int tid = blockIdx.x * blockDim.x + threadIdx.x;
    int stride = gridDim.x * blockDim.x;
    for (int i = tid; i < NN; i += stride) g_deg[i] = 0;
    for (int i = tid; i < NB * RS; i += stride) g_pool[i] = 0.f;
}

// ---------------------------------------------------------------------------
__global__ __launch_bounds__(256) void k_hist(const int* __restrict__ dst) {
    int t = blockIdx.x * blockDim.x + threadIdx.x;
    if (t >= NE / 4) return;
    int4 d4 = __ldg((const int4*)dst + t);
    atomicAdd(&g_deg[d4.x], 1);
    atomicAdd(&g_deg[d4.y], 1);
    atomicAdd(&g_deg[d4.z], 1);
    atomicAdd(&g_deg[d4.w], 1);
}

__global__ __launch_bounds__(256) void k_scanA() {   // per-1024-node PADDED sums
    int t = threadIdx.x, blk = blockIdx.x;
    int base = blk * 1024 + t * 4;
    int s = 0;
#pragma unroll
    for (int j = 0; j < 4; j++) {
        int i = base + j;
        if (i < NN) s += (g_deg[i] + 3) & ~3;
    }
#pragma unroll
    for (int off = 16; off; off >>= 1) s += __shfl_xor_sync(0xffffffffu, s, off);
    __shared__ int ws[8];
    if ((t & 31) == 0) ws[t >> 5] = s;
    __syncthreads();
    if (t == 0) {
        int r = 0;
#pragma unroll
        for (int i = 0; i < 8; i++) r += ws[i];
        g_bsum[blk] = r;
    }
}

// scanC: padded prefix -> start/cursor; fills pad slots with NN (zero row)
__global__ __launch_bounds__(256) void k_scanC() {
    int t = threadIdx.x, blk = blockIdx.x;
    __shared__ int s_pre;
    if (t < 32) {
        int pre = 0;
        for (int i = t; i < blk; i += 32) pre += g_bsum[i];
#pragma unroll
        for (int off = 16; off; off >>= 1) pre += __shfl_xor_sync(0xffffffffu, pre, off);
        if (t == 0) s_pre = pre;
    }
    __syncthreads();
    int base = blk * 1024 + t * 4;
    int degs[4], pads[4]; int tsum = 0;
#pragma unroll
    for (int j = 0; j < 4; j++) {
        int i = base + j;
        degs[j] = (i < NN) ? g_deg[i] : 0;
        pads[j] = (degs[j] + 3) & ~3;
        tsum += pads[j];
    }
    int lane = t & 31, wid = t >> 5;
    int incl = tsum;
#pragma unroll
    for (int off = 1; off < 32; off <<= 1) {
        int u = __shfl_up_sync(0xffffffffu, incl, off);
        if (lane >= off) incl += u;
    }
    __shared__ int ws[8], wo[8];
    if (lane == 31) ws[wid] = incl;
    __syncthreads();
    if (t == 0) { int r = 0; for (int i = 0; i < 8; i++) { wo[i] = r; r += ws[i]; } }
    __syncthreads();
    int excl = s_pre + wo[wid] + incl - tsum;
#pragma unroll
    for (int j = 0; j < 4; j++) {
        int i = base + j;
        if (i < NN) {
            g_start[i] = excl;
            g_cursor[i] = excl;
            for (int p = degs[j]; p < pads[j]; p++) g_adj[excl + p] = NN;
            excl += pads[j];
        }
    }
}

// ---------------------------------------------------------------------------
// Fused: blocks [0, SCAT_BLOCKS) scatter edges; rest run layer-1 GEMM
// (thread-per-node, packed-pair weights in smem, FFMA2).
__global__ __launch_bounds__(256) void k_scatter_gemm(const int* __restrict__ src,
                                                      const int* __restrict__ dst,
                                                      const float* __restrict__ x,
                                                      const float* __restrict__ W1) {
    if (blockIdx.x < SCAT_BLOCKS) {
        int t = blockIdx.x * 256 + threadIdx.x;
        if (t >= NE / 2) return;
        int2 s2 = __ldg((const int2*)src + t);
        int2 d2 = __ldg((const int2*)dst + t);
        int p0 = atomicAdd(&g_cursor[d2.x], 1);
        int p1 = atomicAdd(&g_cursor[d2.y], 1);
        g_adj[p0] = s2.x;
        g_adj[p1] = s2.y;
        return;
    }
    // ---- GEMM path: swp[o2*128 + k] = pack(wt[2o2][k], wt[2o2+1][k]) ----
    __shared__ unsigned long long swp[10 * 128];
    int tid = threadIdx.x;
    for (int i = tid; i < 1280; i += 256) {
        int o2 = i >> 7, k = i & 127;
        int oA = 2 * o2, oB = 2 * o2 + 1;
        float wA = (oA < 10) ? __ldg(&W1[k * 10 + oA]) : __ldg(&W1[(k + 128) * 10 + oA - 10]);
        float wB = (oB < 10) ? __ldg(&W1[k * 10 + oB]) : __ldg(&W1[(k + 128) * 10 + oB - 10]);
        swp[i] = pk2(wA, wB);
    }
    __syncthreads();
    int n = (blockIdx.x - SCAT_BLOCKS) * 256 + tid;
    if (n >= NN) return;
    const float4* xr = (const float4*)(x + (size_t)n * FIN);
    const ulonglong2* swv = (const ulonglong2*)swp;   // swv[o2*64 + k2]
    unsigned long long acc2[10];
#pragma unroll
    for (int o = 0; o < 10; o++) acc2[o] = pk2(0.f, 0.f);
#pragma unroll 4
    for (int k4 = 0; k4 < 32; k4++) {
        float4 xv = __ldg(xr + k4);
        unsigned long long x0 = pk2(xv.x, xv.x), x1 = pk2(xv.y, xv.y);
        unsigned long long x2 = pk2(xv.z, xv.z), x3 = pk2(xv.w, xv.w);
#pragma unroll
        for (int o2 = 0; o2 < 10; o2++) {
            ulonglong2 wa = swv[o2 * 64 + 2 * k4];
            ulonglong2 wb = swv[o2 * 64 + 2 * k4 + 1];
            fma2(acc2[o2], x0, wa.x);
            fma2(acc2[o2], x1, wa.y);
            fma2(acc2[o2], x2, wb.x);
            fma2(acc2[o2], x3, wb.y);
        }
    }
    float2 r[10];
#pragma unroll
    for (int o = 0; o < 10; o++) r[o] = upk2(acc2[o]);
    float* pa = g_xa + (size_t)n * RS;
    *(float4*)(pa)     = make_float4(r[0].x, r[0].y, r[1].x, r[1].y);
    *(float4*)(pa + 4) = make_float4(r[2].x, r[2].y, r[3].x, r[3].y);
    *(float2*)(pa + 8) = make_float2(r[4].x, r[4].y);
    uint4 u;
    u.x = h2u(__floats2half2_rn(r[5].x, r[5].y));
    u.y = h2u(__floats2half2_rn(r[6].x, r[6].y));
    u.z = h2u(__floats2half2_rn(r[7].x, r[7].y));
    u.w = h2u(__floats2half2_rn(r[8].x, r[8].y));
    *(uint4*)(g_xbh + (size_t)n * RH) = u;
    ((unsigned*)(g_xbh + (size_t)n * RH))[4] = h2u(__floats2half2_rn(r[9].x, r[9].y));
}

// ---------------------------------------------------------------------------
__device__ __forceinline__ void red_v4(float* p, float a, float b, float c, float d) {
    asm volatile("red.global.add.v4.f32 [%0], {%1,%2,%3,%4};"
                 :: "l"(p), "f"(a), "f"(b), "f"(c), "f"(d) : "memory");
}

// Pull aggregation, warp per node, fp16 rows, padded adjacency (group-uniform
// bounds), 64 edges of adj preloaded for deep MLP.
// lane = (q = lane>>3 edge slot, idx = lane&7 -> dims 2idx, 2idx+1)
template <int PASS>
__global__ __launch_bounds__(256) void k_aggr(const float* __restrict__ W2) {
    const int lane = threadIdx.x & 31;
    const int n = (blockIdx.x * blockDim.x + threadIdx.x) >> 5;
    if (n >= NN) return;
    const int q = lane >> 3;
    const int idx = lane & 7;

    float wcol[10];
    if (PASS == 0) {
        int col = lane & 15; if (col >= 10) col = 0;
        int off = (lane >> 4) * 10;
#pragma unroll
        for (int k = 0; k < 10; k++) wcol[k] = __ldg(&W2[(k + off) * 10 + col]);
    }

    const int start = g_start[n];
    const int deg = g_deg[n];
    const int degp = (deg + 3) & ~3;
    const int ng = degp >> 2;           // groups of 4 edges, bound is group-uniform
    const __half2* buf = (PASS == 0) ? g_xbh : g_h1bh;

    float a0 = 0.f, a1 = 0.f;
    int av0 = __ldg(&g_adj[start + lane]);                          // edges 0-31
    int av1 = (degp > 32) ? __ldg(&g_adj[start + 32 + lane]) : 0;   // edges 32-63
#pragma unroll
    for (int g = 0; g < 8; g++) {
        if (g < ng) {
            int s = __shfl_sync(0xffffffffu, av0, 4 * g + q);
            float2 f = __half22float2(__ldg(&buf[(size_t)s * RH + idx]));
            a0 += f.x; a1 += f.y;
        }
    }
#pragma unroll
    for (int g = 8; g < 16; g++) {
        if (g < ng) {
            int s = __shfl_sync(0xffffffffu, av1, 4 * (g - 8) + q);
            float2 f = __half22float2(__ldg(&buf[(size_t)s * RH + idx]));
            a0 += f.x; a1 += f.y;
        }
    }
    for (int base = 64; base < degp; base += 32) {                  // rare tail
        int av = __ldg(&g_adj[start + base + lane]);
        int ng2 = (degp - base) >> 2; if (ng2 > 8) ng2 = 8;
#pragma unroll
        for (int g = 0; g < 8; g++) {
            if (g < ng2) {
                int s = __shfl_sync(0xffffffffu, av, 4 * g + q);
                float2 f = __half22float2(__ldg(&buf[(size_t)s * RH + idx]));
                a0 += f.x; a1 += f.y;
            }
        }
    }
    a0 += __shfl_xor_sync(0xffffffffu, a0, 8);
    a0 += __shfl_xor_sync(0xffffffffu, a0, 16);
    a1 += __shfl_xor_sync(0xffffffffu, a1, 8);
    a1 += __shfl_xor_sync(0xffffffffu, a1, 16);

    const float inv = deg > 0 ? 1.f / (float)deg : 0.f;

    if (PASS == 0) {
        float2 xs = *(const float2*)(g_xa + (size_t)n * RS + 2 * idx);
        float h0 = fmaxf(xs.x + a0 * inv, 0.f);   // dim 2*idx
        float h1 = fmaxf(xs.y + a1 * inv, 0.f);   // dim 2*idx+1
        float o = 0.f;
#pragma unroll
        for (int k = 0; k < 10; k++) {
            float hk = (k & 1) ? __shfl_sync(0xffffffffu, h1, k >> 1)
                               : __shfl_sync(0xffffffffu, h0, k >> 1);
            o += hk * wcol[k];
        }
        int dim = lane & 15;
        float onext = __shfl_down_sync(0xffffffffu, o, 1);
        if (lane < 16) {                         // h1a, fp32
            if (dim < 10) g_h1a[(size_t)n * RS + dim] = o;
        } else if ((dim & 1) == 0 && dim < 10) { // h1b, fp16 packed
            g_h1bh[(size_t)n * RH + (dim >> 1)] = __floats2half2_rn(o, onext);
        }
    } else {
        if (lane < 5) {                          // q==0, idx 0-4 -> dims 0-9
            float2 ar = *(const float2*)(g_h1a + (size_t)n * RS + 2 * idx);
            float2 h2v;
            h2v.x = ar.x + a0 * inv;
            h2v.y = ar.y + a1 * inv;
            *(float2*)(g_h2 + (size_t)n * RS + 2 * idx) = h2v;
        }
    }
}

// ---------------------------------------------------------------------------
// Pool h2 by sorted batch id with warp aggregation.
__global__ __launch_bounds__(256) void k_final(const int* __restrict__ batch) {
    int n = blockIdx.x * blockDim.x + threadIdx.x;
    if (n >= NN) return;            // NN % 32 == 0
    int lane = threadIdx.x & 31;
    const float4* hr = (const float4*)(g_h2 + (size_t)n * RS);
    float4 h0 = __ldg(hr), h1 = __ldg(hr + 1);
    float2 h2 = __ldg((const float2*)(hr + 2));
    float h[10] = {h0.x, h0.y, h0.z, h0.w, h1.x, h1.y, h1.z, h1.w, h2.x, h2.y};
    int b = __ldg(&batch[n]);
    int b0 = __shfl_sync(0xffffffffu, b, 0);
    bool uni = __all_sync(0xffffffffu, b == b0);
    if (uni) {
#pragma unroll
        for (int off = 16; off; off >>= 1)
#pragma unroll
            for (int o = 0; o < 10; o++)
                h[o] += __shfl_xor_sync(0xffffffffu, h[o], off);
        if (lane == 0) {
            float* pp = g_pool + b * RS;
            red_v4(pp,     h[0], h[1], h[2], h[3]);
            red_v4(pp + 4, h[4], h[5], h[6], h[7]);
            red_v4(pp + 8, h[8], h[9], 32.f, 0.f);
        }
    } else {
        float* pp = g_pool + b * RS;
#pragma unroll
        for (int o = 0; o < 10; o++) atomicAdd(&pp[o], h[o]);
        atomicAdd(&pp[10], 1.f);
    }
}

// ---------------------------------------------------------------------------
__global__ void k_head(const float* __restrict__ Wfc, float* __restrict__ out) {
    int b = blockIdx.x * blockDim.x + threadIdx.x;
    if (b >= NB) return;
    float inv = 1.f / fmaxf(g_pool[b * RS + 10], 1.f);
    float v = 0.f;
#pragma unroll
    for (int o = 0; o < 10; o++)
        v += g_pool[b * RS + o] * inv * __ldg(&Wfc[o]);
    out[b] = 1.f / (1.f + expf(-v));
}

// ---------------------------------------------------------------------------
extern "C" void kernel_launch(void* const* d_in, const int* in_sizes, int n_in,
                              void* d_out, int out_size) {
    const float* x     = (const float*)d_in[0];
    const int*   ei    = (const int*)d_in[1];   // [2, E]
    const int*   batch = (const int*)d_in[2];
    const float* W1    = (const float*)d_in[3]; // [256,10]
    const float* W2    = (const float*)d_in[4]; // [20,10]
    const float* Wfc   = (const float*)d_in[5]; // [10,1]
    float* out = (float*)d_out;

    const int* src = ei;
    const int* dst = ei + NE;

    k_zero<<<256, 256>>>();
    k_hist<<<(NE / 4 + 255) / 256, 256>>>(dst);
    k_scanA<<<NBLK, 256>>>();
    k_scanC<<<NBLK, 256>>>();
    k_scatter_gemm<<<SCAT_BLOCKS + GEMM_BLOCKS, 256>>>(src, dst, x, W1);
    k_aggr<0><<<(NN * 32 + 255) / 256, 256>>>(W2);
    k_aggr<1><<<(NN * 32 + 255) / 256, 256>>>(W2);
    k_final<<<(NN + 255) / 256, 256>>>(batch);
    k_head<<<(NB + 255) / 256, 256>>>(Wfc, out);
}